// round 13
// baseline (speedup 1.0000x reference)
#include <cuda_runtime.h>
#include <cstdint>
#include <math.h>

// y_true [B,1024] fp32, target [B,1024] fp32 -> scalar fp32 loss.
#define NCOLS   1024
#define NBLK    444            // 148 SMs * 3 resident blocks (80 regs/thread)
#define NWARPS  (NBLK * 8)

__device__ double g_pt[NBLK];
__device__ double g_ce[NBLK];
__device__ unsigned int g_count = 0;   // last-block-done counter

__device__ __forceinline__ float wval(int x) {
    const int pc = __popc(x);
    float w = ((pc & 1) ? 6.0f       : 1.0f)
            * ((pc & 2) ? 36.0f      : 1.0f)
            * ((pc & 4) ? 1296.0f    : 1.0f)
            * ((pc & 8) ? 1679616.0f : 1.0f);
    return (x == 0) ? 0.0f : w;   // 6^popc(x), zeroed at x==0; exact in fp32
}

// ---------------------------------------------------------------------------
// One-row software pipeline (R11) + interleaved FMA/next-y-load:
//   (1) issue target loads row b+1
//   (2) REDUX on carried (best,bidx) -> t for row b       [no wait]
//   (3/4) per element: FMA carried yv[i] (row b), then immediately reload
//         yv[i] from row b+1 (WAR-safe, zero extra registers) -> y loads
//         start issuing 4 FMAs into the phase instead of after all 32
//   (5) per-lane compare on (1)'s data -> carried (best,bidx) for b+1
// ---------------------------------------------------------------------------
__global__ void __launch_bounds__(256, 3)
fused_kernel(const float* __restrict__ y, const float* __restrict__ target,
             float* __restrict__ out, int B) {
    // W[p][i] = wval(i ^ p): weights of columns 4g..4g+3 for class t are the
    // aligned float4 at W[t&3][4*(g ^ (t>>2))].
    __shared__ float W[4][NCOLS];
    const int tid  = threadIdx.x;
    const int lane = tid & 31;
    const int wid  = tid >> 5;
    for (int i = tid; i < NCOLS; i += 256) {
        #pragma unroll
        for (int p = 0; p < 4; p++) W[p][i] = wval(i ^ p);
    }
    __syncthreads();

    const int gwarp = blockIdx.x * 8 + wid;
    float pt32 = 0.0f;   // fp32 within-warp is exact enough (budget ~140 abs)
    float ce32 = 0.0f;

    int   b = gwarp;
    float best = -1.0f;
    int   bidx = 0;
    float4 yv[8];

    if (b < B) {
        // Prologue: load row b's target + y; per-lane argmax of target.
        const float4* tp = reinterpret_cast<const float4*>(target + (size_t)b * NCOLS);
        const float4* yp = reinterpret_cast<const float4*>(y      + (size_t)b * NCOLS);
        float4 tv[8];
        #pragma unroll
        for (int i = 0; i < 8; i++) {
            tv[i] = __ldcs(&tp[i * 32 + lane]);
            yv[i] = __ldcs(&yp[i * 32 + lane]);
        }
        #pragma unroll
        for (int i = 0; i < 8; i++) {
            const int base = (i * 32 + lane) * 4;
            if (tv[i].x > best) { best = tv[i].x; bidx = base;     }
            if (tv[i].y > best) { best = tv[i].y; bidx = base + 1; }
            if (tv[i].z > best) { best = tv[i].z; bidx = base + 2; }
            if (tv[i].w > best) { best = tv[i].w; bidx = base + 3; }
        }

        // Steady-state pipeline.
        for (;;) {
            int bn = b + NWARPS;
            const bool last = (bn >= B);
            if (last) bn = b;   // clamped prefetch: loaded but never accumulated
            const float4* tpn = reinterpret_cast<const float4*>(target + (size_t)bn * NCOLS);
            const float4* ypn = reinterpret_cast<const float4*>(y      + (size_t)bn * NCOLS);

            // (1) issue next target row loads.
            float4 tn[8];
            #pragma unroll
            for (int i = 0; i < 8; i++) tn[i] = __ldcs(&tpn[i * 32 + lane]);

            // (2) cross-lane argmax for row b from carried (best,bidx): no wait.
            const unsigned int mybits  = __float_as_uint(best);
            const unsigned int maxbits = __reduce_max_sync(0xffffffffu, mybits);
            const unsigned int cand    = (mybits == maxbits) ? (unsigned int)bidx
                                                             : 0xffffffffu;
            const int t  = (int)__reduce_min_sync(0xffffffffu, cand);
            const int tg = t >> 2;
            const float* Wt = W[t & 3];

            // (3/4) interleaved: FMA carried yv[i] (row b), then immediately
            // reload yv[i] with row b+1's value (register reused in place).
            float s0 = 0.f, s1 = 0.f, s2 = 0.f, s3 = 0.f;
            float yt = -1.0f;
            #pragma unroll
            for (int i = 0; i < 8; i++) {
                const int c4 = i * 32 + lane;
                const float4 w4 = *reinterpret_cast<const float4*>(&Wt[(c4 ^ tg) << 2]);
                s0 += w4.x * yv[i].x;
                s1 += w4.y * yv[i].y;
                s2 += w4.z * yv[i].z;
                s3 += w4.w * yv[i].w;
                if (c4 == tg) {
                    yt = (t & 1) ? ((t & 2) ? yv[i].w : yv[i].y)
                                 : ((t & 2) ? yv[i].z : yv[i].x);
                }
                yv[i] = __ldcs(&ypn[c4]);   // issue next-row load right away
            }
            pt32 += (s0 + s1) + (s2 + s3);
            if (yt >= 0.0f) ce32 += __logf(yt + 1e-8f);   // one lane per warp

            // (5) per-lane compare on next target row (wait covered by 2-4).
            best = -1.0f; bidx = 0;
            #pragma unroll
            for (int i = 0; i < 8; i++) {
                const int base = (i * 32 + lane) * 4;
                if (tn[i].x > best) { best = tn[i].x; bidx = base;     }
                if (tn[i].y > best) { best = tn[i].y; bidx = base + 1; }
                if (tn[i].z > best) { best = tn[i].z; bidx = base + 2; }
                if (tn[i].w > best) { best = tn[i].w; bidx = base + 3; }
            }

            if (last) break;
            b = bn;
        }
    }

    // Warp reduce in fp32 (fixed order), promote to double for partials.
    #pragma unroll
    for (int off = 16; off > 0; off >>= 1) {
        pt32 += __shfl_down_sync(0xffffffffu, pt32, off);
        ce32 += __shfl_down_sync(0xffffffffu, ce32, off);
    }
    __shared__ double s_pt[8];
    __shared__ double s_ce[8];
    if (lane == 0) { s_pt[wid] = (double)pt32; s_ce[wid] = (double)ce32; }
    __syncthreads();
    __shared__ bool is_last;
    if (tid == 0) {
        double bpt = 0.0, bce = 0.0;
        #pragma unroll
        for (int i = 0; i < 8; i++) { bpt += s_pt[i]; bce += s_ce[i]; }
        g_pt[blockIdx.x] = bpt;
        g_ce[blockIdx.x] = bce;
        __threadfence();
        const unsigned int arrived = atomicAdd(&g_count, 1u);
        is_last = (arrived == NBLK - 1);
    }
    __syncthreads();

    // Last block: final fixed-order reduction -> scalar loss.
    if (is_last) {
        double fpt = 0.0, fce = 0.0;
        for (int i = tid; i < NBLK; i += 256) { fpt += g_pt[i]; fce += g_ce[i]; }
        __shared__ double r_pt[256];
        __shared__ double r_ce[256];
        r_pt[tid] = fpt;
        r_ce[tid] = fce;
        __syncthreads();
        #pragma unroll
        for (int off = 128; off > 0; off >>= 1) {
            if (tid < off) {
                r_pt[tid] += r_pt[tid + off];
                r_ce[tid] += r_ce[tid + off];
            }
            __syncthreads();
        }
        if (tid == 0) {
            const double pt_loss = r_pt[0] / ((double)B * (double)NCOLS);
            const double ce_loss = -r_ce[0] / (double)B;
            out[0] = (float)(ce_loss + pt_loss);
            g_count = 0;   // reset for next graph replay
        }
    }
}

extern "C" void kernel_launch(void* const* d_in, const int* in_sizes, int n_in,
                              void* d_out, int out_size) {
    const float* y_true = (const float*)d_in[0];
    const float* target = (const float*)d_in[1];
    const int B = in_sizes[0] / NCOLS;

    fused_kernel<<<NBLK, 256>>>(y_true, target, (float*)d_out, B);
}

// round 14
// speedup vs baseline: 1.0479x; 1.0479x over previous
#include <cuda_runtime.h>
#include <cstdint>
#include <math.h>

// y_true [B,1024] fp32, target [B,1024] fp32 -> scalar fp32 loss.
#define NCOLS   1024
#define NBLK    444            // 148 SMs * 3 resident blocks (80 regs/thread)
#define NWARPS  (NBLK * 8)

__device__ double g_pt[NBLK];
__device__ double g_ce[NBLK];
__device__ unsigned int g_count = 0;   // last-block-done counter

__device__ __forceinline__ float wval(int x) {
    const int pc = __popc(x);
    float w = ((pc & 1) ? 6.0f       : 1.0f)
            * ((pc & 2) ? 36.0f      : 1.0f)
            * ((pc & 4) ? 1296.0f    : 1.0f)
            * ((pc & 8) ? 1679616.0f : 1.0f);
    return (x == 0) ? 0.0f : w;   // 6^popc(x), zeroed at x==0; exact in fp32
}

// ---------------------------------------------------------------------------
// One-row software pipeline: everything consumed in iteration i was issued in
// iteration i-1, so REDUX and FMA phases never wait on memory. Per iteration:
//   (1) issue target loads row b+1   (2) REDUX on carried (best,bidx) -> t_b
//   (3) FMA carried yv (row b)       (4) issue y loads row b+1
//   (5) per-lane compare on (1)'s data -> carried (best,bidx) for b+1
// Loads stay front-batched (8 LDG.128 per batch) — proven critical: any
// structure that interleaves loads into compute loses (R5/R6/R13).
// ---------------------------------------------------------------------------
__global__ void __launch_bounds__(256, 3)
fused_kernel(const float* __restrict__ y, const float* __restrict__ target,
             float* __restrict__ out, int B) {
    // W[p][i] = wval(i ^ p): weights of columns 4g..4g+3 for class t are the
    // aligned float4 at W[t&3][4*(g ^ (t>>2))].
    __shared__ float W[4][NCOLS];
    const int tid  = threadIdx.x;
    const int lane = tid & 31;
    const int wid  = tid >> 5;
    for (int i = tid; i < NCOLS; i += 256) {
        #pragma unroll
        for (int p = 0; p < 4; p++) W[p][i] = wval(i ^ p);
    }
    __syncthreads();

    const int gwarp = blockIdx.x * 8 + wid;
    float pt32 = 0.0f;   // fp32 within-warp is exact enough (budget ~140 abs)
    float ce32 = 0.0f;

    int   b = gwarp;
    float best = -1.0f;
    int   bidx = 0;
    float4 yv[8];

    if (b < B) {
        // Prologue: load row b's target + y; per-lane argmax of target.
        const float4* tp = reinterpret_cast<const float4*>(target + (size_t)b * NCOLS);
        const float4* yp = reinterpret_cast<const float4*>(y      + (size_t)b * NCOLS);
        float4 tv[8];
        #pragma unroll
        for (int i = 0; i < 8; i++) {
            tv[i] = __ldcs(&tp[i * 32 + lane]);
            yv[i] = __ldcs(&yp[i * 32 + lane]);
        }
        #pragma unroll
        for (int i = 0; i < 8; i++) {
            const int base = (i * 32 + lane) * 4;
            if (tv[i].x > best) { best = tv[i].x; bidx = base;     }
            if (tv[i].y > best) { best = tv[i].y; bidx = base + 1; }
            if (tv[i].z > best) { best = tv[i].z; bidx = base + 2; }
            if (tv[i].w > best) { best = tv[i].w; bidx = base + 3; }
        }

        // Steady-state pipeline.
        for (;;) {
            int bn = b + NWARPS;
            const bool last = (bn >= B);
            if (last) bn = b;   // clamped prefetch: loaded but never accumulated
            const float4* tpn = reinterpret_cast<const float4*>(target + (size_t)bn * NCOLS);
            const float4* ypn = reinterpret_cast<const float4*>(y      + (size_t)bn * NCOLS);

            // (1) issue next target row loads.
            float4 tn[8];
            #pragma unroll
            for (int i = 0; i < 8; i++) tn[i] = __ldcs(&tpn[i * 32 + lane]);

            // (2) cross-lane argmax for row b from carried (best,bidx): no wait.
            const unsigned int mybits  = __float_as_uint(best);
            const unsigned int maxbits = __reduce_max_sync(0xffffffffu, mybits);
            const unsigned int cand    = (mybits == maxbits) ? (unsigned int)bidx
                                                             : 0xffffffffu;
            const int t  = (int)__reduce_min_sync(0xffffffffu, cand);
            const int tg = t >> 2;
            const float* Wt = W[t & 3];

            // (3) FMA carried yv (row b, loaded one iteration ago): no wait.
            float s0 = 0.f, s1 = 0.f, s2 = 0.f, s3 = 0.f;
            float yt = -1.0f;
            #pragma unroll
            for (int i = 0; i < 8; i++) {
                const int c4 = i * 32 + lane;
                const float4 w4 = *reinterpret_cast<const float4*>(&Wt[(c4 ^ tg) << 2]);
                s0 += w4.x * yv[i].x;
                s1 += w4.y * yv[i].y;
                s2 += w4.z * yv[i].z;
                s3 += w4.w * yv[i].w;
                if (c4 == tg) {
                    yt = (t & 1) ? ((t & 2) ? yv[i].w : yv[i].y)
                                 : ((t & 2) ? yv[i].z : yv[i].x);
                }
            }
            pt32 += (s0 + s1) + (s2 + s3);
            if (yt >= 0.0f) ce32 += __logf(yt + 1e-8f);   // one lane per warp

            // (4) issue next y row loads (yv consumed above; full iter to land).
            #pragma unroll
            for (int i = 0; i < 8; i++) yv[i] = __ldcs(&ypn[i * 32 + lane]);

            // (5) per-lane compare on next target row (wait covered by 2-4).
            best = -1.0f; bidx = 0;
            #pragma unroll
            for (int i = 0; i < 8; i++) {
                const int base = (i * 32 + lane) * 4;
                if (tn[i].x > best) { best = tn[i].x; bidx = base;     }
                if (tn[i].y > best) { best = tn[i].y; bidx = base + 1; }
                if (tn[i].z > best) { best = tn[i].z; bidx = base + 2; }
                if (tn[i].w > best) { best = tn[i].w; bidx = base + 3; }
            }

            if (last) break;
            b = bn;
        }
    }

    // Warp reduce in fp32 (fixed order), promote to double for partials.
    #pragma unroll
    for (int off = 16; off > 0; off >>= 1) {
        pt32 += __shfl_down_sync(0xffffffffu, pt32, off);
        ce32 += __shfl_down_sync(0xffffffffu, ce32, off);
    }
    __shared__ double s_pt[8];
    __shared__ double s_ce[8];
    if (lane == 0) { s_pt[wid] = (double)pt32; s_ce[wid] = (double)ce32; }
    __syncthreads();
    __shared__ bool is_last;
    if (tid == 0) {
        double bpt = 0.0, bce = 0.0;
        #pragma unroll
        for (int i = 0; i < 8; i++) { bpt += s_pt[i]; bce += s_ce[i]; }
        g_pt[blockIdx.x] = bpt;
        g_ce[blockIdx.x] = bce;
        __threadfence();
        const unsigned int arrived = atomicAdd(&g_count, 1u);
        is_last = (arrived == NBLK - 1);
    }
    __syncthreads();

    // Last block: final fixed-order reduction -> scalar loss.
    if (is_last) {
        double fpt = 0.0, fce = 0.0;
        for (int i = tid; i < NBLK; i += 256) { fpt += g_pt[i]; fce += g_ce[i]; }
        __shared__ double r_pt[256];
        __shared__ double r_ce[256];
        r_pt[tid] = fpt;
        r_ce[tid] = fce;
        __syncthreads();
        #pragma unroll
        for (int off = 128; off > 0; off >>= 1) {
            if (tid < off) {
                r_pt[tid] += r_pt[tid + off];
                r_ce[tid] += r_ce[tid + off];
            }
            __syncthreads();
        }
        if (tid == 0) {
            const double pt_loss = r_pt[0] / ((double)B * (double)NCOLS);
            const double ce_loss = -r_ce[0] / (double)B;
            out[0] = (float)(ce_loss + pt_loss);
            g_count = 0;   // reset for next graph replay
        }
    }
}

extern "C" void kernel_launch(void* const* d_in, const int* in_sizes, int n_in,
                              void* d_out, int out_size) {
    const float* y_true = (const float*)d_in[0];
    const float* target = (const float*)d_in[1];
    const int B = in_sizes[0] / NCOLS;

    fused_kernel<<<NBLK, 256>>>(y_true, target, (float*)d_out, B);
}